// round 5
// baseline (speedup 1.0000x reference)
#include <cuda_runtime.h>
#include <cstdint>

// ---------------------------------------------------------------------------
// BaseGCN round 4: pre-scaled activations (no cnorm), fused agg+GEMM with
// smem z tile, fused CSR-build helpers. 10 kernel launches total.
//   hs = dinv * prelu(z @ W + b)   (pre-scaled activations)
//   z[v] = dinv[v] * ( sum_{s in N(v)} hs[s] + hs[v] )
// ---------------------------------------------------------------------------

#define NMAX 100352
#define EMAX 1600000
#define SCAN_BLK 1024

__device__ float g_dinv[NMAX];
__device__ int   g_deg [NMAX];
__device__ int   g_fill[NMAX];
__device__ int   g_rowptr[NMAX + 1];
__device__ int   g_bsums[256];
__device__ int   g_col  [EMAX];
__device__ float g_xs[(size_t)NMAX * 8];    // dinv-scaled input features
__device__ float g_ha[(size_t)NMAX * 64];   // pre-scaled activations (ping)
__device__ float g_hb[(size_t)NMAX * 64];   // pre-scaled activations (pong)
__device__ float g_z [(size_t)NMAX * 64];   // layer-4 aggregate for pooling
__device__ float g_Wc[64 * 4];              // W4 @ Wlin
__device__ float g_bc[4];                   // b4 @ Wlin + blin

static inline int cdiv(long a, long b) { return (int)((a + b - 1) / b); }

// ---------------- CSR build ----------------
__global__ void k_zero(int* __restrict__ deg, int* __restrict__ fill, int n) {
    int i = blockIdx.x * blockDim.x + threadIdx.x;
    if (i < n) { deg[i] = 0; fill[i] = 0; }
}

__global__ void k_count(const int* __restrict__ dst, int* __restrict__ deg, int e) {
    int i = blockIdx.x * blockDim.x + threadIdx.x;
    if (i < e) atomicAdd(&deg[dst[i]], 1);
}

// exclusive scan of deg -> rowptr (per block), block sums -> bsums; also dinv.
__global__ void k_scan1(const int* __restrict__ deg, int* __restrict__ rowptr,
                        int* __restrict__ bsums, float* __restrict__ dinv, int n) {
    __shared__ int sm[SCAN_BLK];
    int i = blockIdx.x * SCAN_BLK + threadIdx.x;
    int v = (i < n) ? deg[i] : 0;
    if (i < n) dinv[i] = rsqrtf((float)v + 1.0f);        // +1 self-loop
    sm[threadIdx.x] = v;
    __syncthreads();
#pragma unroll
    for (int off = 1; off < SCAN_BLK; off <<= 1) {
        int t = (threadIdx.x >= off) ? sm[threadIdx.x - off] : 0;
        __syncthreads();
        sm[threadIdx.x] += t;
        __syncthreads();
    }
    if (i < n) rowptr[i] = sm[threadIdx.x] - v;          // exclusive
    if (threadIdx.x == SCAN_BLK - 1) bsums[blockIdx.x] = sm[SCAN_BLK - 1];
}

__global__ void k_scan2(int* __restrict__ bsums, int nb) {
    __shared__ int sm[256];
    int v = (threadIdx.x < nb) ? bsums[threadIdx.x] : 0;
    sm[threadIdx.x] = v;
    __syncthreads();
#pragma unroll
    for (int off = 1; off < 256; off <<= 1) {
        int t = (threadIdx.x >= off) ? sm[threadIdx.x - off] : 0;
        __syncthreads();
        sm[threadIdx.x] += t;
        __syncthreads();
    }
    if (threadIdx.x < nb) bsums[threadIdx.x] = sm[threadIdx.x] - v;  // exclusive
}

// finalize rowptr; also write xs = dinv * x (layer-1 pre-scaled input)
__global__ void k_scan3(int* __restrict__ rowptr, const int* __restrict__ bsums,
                        const float* __restrict__ x, const float* __restrict__ dinv,
                        float* __restrict__ xs, int n, int e) {
    int i = blockIdx.x * blockDim.x + threadIdx.x;
    if (i >= n) { if (i == n) rowptr[n] = e; return; }
    rowptr[i] += bsums[i / SCAN_BLK];
    if (i == 0) rowptr[n] = e;
    float d = __ldg(&dinv[i]);
    const float4* x4 = reinterpret_cast<const float4*>(x) + (size_t)i * 2;
    float4* s4 = reinterpret_cast<float4*>(xs) + (size_t)i * 2;
    float4 a = __ldg(x4), b = __ldg(x4 + 1);
    a.x *= d; a.y *= d; a.z *= d; a.w *= d;
    b.x *= d; b.y *= d; b.z *= d; b.w *= d;
    s4[0] = a; s4[1] = b;
}

__global__ void k_fillcsr(const int* __restrict__ src, const int* __restrict__ dst,
                          const int* __restrict__ rowptr, int* __restrict__ fill,
                          int* __restrict__ col, int e) {
    int i = blockIdx.x * blockDim.x + threadIdx.x;
    if (i >= e) return;
    int d = dst[i];
    int pos = __ldg(&rowptr[d]) + atomicAdd(&fill[d], 1);
    col[pos] = src[i];
}

// ---------------- head precompose: Wc = W4 @ Wlin, bc = b4 @ Wlin + blin ----
__global__ void k_head(const float* __restrict__ W4, const float* __restrict__ b4,
                       const float* __restrict__ Wlin, const float* __restrict__ blin,
                       float* __restrict__ Wc, float* __restrict__ bc) {
    int t = threadIdx.x;
    int i = t >> 2, c = t & 3;
    float s = 0.f;
#pragma unroll 8
    for (int k = 0; k < 128; k++)
        s += __ldg(&W4[i * 128 + k]) * __ldg(&Wlin[k * 4 + c]);
    Wc[i * 4 + c] = s;
    if (i == 0) {
        float b = __ldg(&blin[c]);
#pragma unroll 8
        for (int k = 0; k < 128; k++)
            b += __ldg(&b4[k]) * __ldg(&Wlin[k * 4 + c]);
        bc[c] = b;
    }
}

// ---------------- fused agg + GEMM + PReLU + prescale ----------------------
// Phase 1 (per TPE-group): zs = dinv*(sum_{nbr} hs + hs[self]) into smem.
// Phase 2: h_out = dinv * prelu(zs @ W + b), written pre-scaled.
template<int FIN, int FOUT>
__global__ void __launch_bounds__(256)
k_layer(const int* __restrict__ rowptr, const int* __restrict__ col,
        const float* __restrict__ hs, const float* __restrict__ dinv,
        const float* __restrict__ W, const float* __restrict__ bias,
        const float* __restrict__ aP, float* __restrict__ out, int n) {
    constexpr int TPE = FIN / 4;
    constexpr int NPB = 256 / TPE;
    __shared__ float zs[NPB][FIN];
    __shared__ float Ws[FIN * FOUT];
    __shared__ float bs[FOUT];

    for (int i = threadIdx.x; i < FIN * FOUT; i += 256) Ws[i] = __ldg(&W[i]);
    if (threadIdx.x < FOUT) bs[threadIdx.x] = __ldg(&bias[threadIdx.x]);
    float a = __ldg(aP);

    int group = threadIdx.x / TPE;
    int lane  = threadIdx.x % TPE;
    int node  = blockIdx.x * NPB + group;

    const float4* h4 = reinterpret_cast<const float4*>(hs);
    if (node < n) {
        int beg = __ldg(&rowptr[node]);
        int end = __ldg(&rowptr[node + 1]);
        float4 acc = __ldg(h4 + (size_t)node * TPE + lane);   // self (pre-scaled)
        int p = beg;
        for (; p + 4 <= end; p += 4) {
            int s0 = __ldg(&col[p + 0]);
            int s1 = __ldg(&col[p + 1]);
            int s2 = __ldg(&col[p + 2]);
            int s3 = __ldg(&col[p + 3]);
            float4 v0 = __ldg(h4 + (size_t)s0 * TPE + lane);
            float4 v1 = __ldg(h4 + (size_t)s1 * TPE + lane);
            float4 v2 = __ldg(h4 + (size_t)s2 * TPE + lane);
            float4 v3 = __ldg(h4 + (size_t)s3 * TPE + lane);
            acc.x += v0.x + v1.x + v2.x + v3.x;
            acc.y += v0.y + v1.y + v2.y + v3.y;
            acc.z += v0.z + v1.z + v2.z + v3.z;
            acc.w += v0.w + v1.w + v2.w + v3.w;
        }
        for (; p < end; p++) {
            int s = __ldg(&col[p]);
            float4 v = __ldg(h4 + (size_t)s * TPE + lane);
            acc.x += v.x; acc.y += v.y; acc.z += v.z; acc.w += v.w;
        }
        float d = __ldg(&dinv[node]);
        acc.x *= d; acc.y *= d; acc.z *= d; acc.w *= d;
        *reinterpret_cast<float4*>(&zs[group][lane * 4]) = acc;
    }
    __syncthreads();

    // Phase 2: NPB*FOUT/4 float4 outputs, 256 threads
    constexpr int NV4 = NPB * FOUT / 4;       // = 512 for all three layers
#pragma unroll
    for (int j = 0; j < NV4 / 256; j++) {
        int idx = threadIdx.x + j * 256;
        int gi  = idx / (FOUT / 4);           // node within block
        int c4  = idx % (FOUT / 4);
        int gnode = blockIdx.x * NPB + gi;
        if (gnode >= n) continue;
        int c = c4 * 4;
        float4 acc = {bs[c], bs[c + 1], bs[c + 2], bs[c + 3]};
#pragma unroll
        for (int k = 0; k < FIN; k++) {
            float zk = zs[gi][k];
            float4 w = *reinterpret_cast<const float4*>(&Ws[k * FOUT + c]);
            acc.x += zk * w.x; acc.y += zk * w.y;
            acc.z += zk * w.z; acc.w += zk * w.w;
        }
        acc.x = acc.x >= 0.f ? acc.x : a * acc.x;
        acc.y = acc.y >= 0.f ? acc.y : a * acc.y;
        acc.z = acc.z >= 0.f ? acc.z : a * acc.z;
        acc.w = acc.w >= 0.f ? acc.w : a * acc.w;
        float d = __ldg(&dinv[gnode]);
        acc.x *= d; acc.y *= d; acc.z *= d; acc.w *= d;
        reinterpret_cast<float4*>(out)[(size_t)gnode * (FOUT / 4) + c4] = acc;
    }
}

// ---------------- layer-4 aggregation only (true z, 64-wide) ----------------
__global__ void __launch_bounds__(256)
k_agg64(const int* __restrict__ rowptr, const int* __restrict__ col,
        const float* __restrict__ hs, const float* __restrict__ dinv,
        float* __restrict__ z, int n) {
    constexpr int TPE = 16;
    long gid = (long)blockIdx.x * blockDim.x + threadIdx.x;
    int node = (int)(gid / TPE);
    int lane = (int)(gid % TPE);
    if (node >= n) return;

    int beg = __ldg(&rowptr[node]);
    int end = __ldg(&rowptr[node + 1]);
    const float4* h4 = reinterpret_cast<const float4*>(hs);
    float4 acc = __ldg(h4 + (size_t)node * TPE + lane);   // self (pre-scaled)
    int p = beg;
    for (; p + 4 <= end; p += 4) {
        int s0 = __ldg(&col[p + 0]);
        int s1 = __ldg(&col[p + 1]);
        int s2 = __ldg(&col[p + 2]);
        int s3 = __ldg(&col[p + 3]);
        float4 v0 = __ldg(h4 + (size_t)s0 * TPE + lane);
        float4 v1 = __ldg(h4 + (size_t)s1 * TPE + lane);
        float4 v2 = __ldg(h4 + (size_t)s2 * TPE + lane);
        float4 v3 = __ldg(h4 + (size_t)s3 * TPE + lane);
        acc.x += v0.x + v1.x + v2.x + v3.x;
        acc.y += v0.y + v1.y + v2.y + v3.y;
        acc.z += v0.z + v1.z + v2.z + v3.z;
        acc.w += v0.w + v1.w + v2.w + v3.w;
    }
    for (; p < end; p++) {
        int s = __ldg(&col[p]);
        float4 v = __ldg(h4 + (size_t)s * TPE + lane);
        acc.x += v.x; acc.y += v.y; acc.z += v.z; acc.w += v.w;
    }
    float d = __ldg(&dinv[node]);
    acc.x *= d; acc.y *= d; acc.z *= d; acc.w *= d;
    reinterpret_cast<float4*>(z)[(size_t)node * TPE + lane] = acc;
}

// ---------------- pool (64-wide mean per graph) + composed head -------------
__device__ __forceinline__ int lower_bound_i(const int* b, int n, int v) {
    int lo = 0, hi = n;
    while (lo < hi) {
        int m = (lo + hi) >> 1;
        if (__ldg(&b[m]) < v) lo = m + 1; else hi = m;
    }
    return lo;
}

__global__ void k_pool(const float* __restrict__ z, const int* __restrict__ batch,
                       const float* __restrict__ Wc, const float* __restrict__ bc,
                       float* __restrict__ out, int n) {
    const int F = 64;
    int g = blockIdx.x;
    int start = lower_bound_i(batch, n, g);
    int end   = lower_bound_i(batch, n, g + 1);

    int c   = threadIdx.x & (F - 1);
    int sub = threadIdx.x >> 6;
    float acc = 0.f;
    for (int r = start + sub; r < end; r += 4)
        acc += __ldg(&z[(size_t)r * F + c]);

    __shared__ float sm[256];
    __shared__ float pooled[F];
    sm[threadIdx.x] = acc;
    __syncthreads();
    if (threadIdx.x < F) {
        int cnt = end - start;
        float denom = (float)(cnt > 1 ? cnt : 1);
        pooled[threadIdx.x] = (sm[threadIdx.x] + sm[threadIdx.x + 64] +
                               sm[threadIdx.x + 128] + sm[threadIdx.x + 192]) / denom;
    }
    __syncthreads();
    if (threadIdx.x < 4) {
        float s = __ldg(&bc[threadIdx.x]);
#pragma unroll 8
        for (int f = 0; f < F; f++)
            s += pooled[f] * __ldg(&Wc[f * 4 + threadIdx.x]);
        out[g * 4 + threadIdx.x] = s;
    }
}

// ---------------------------------------------------------------------------
extern "C" void kernel_launch(void* const* d_in, const int* in_sizes, int n_in,
                              void* d_out, int out_size) {
    const float* x    = (const float*)d_in[0];
    const int* esrc   = (const int*)d_in[1];
    const int* edst   = (const int*)d_in[2];
    const int* batch  = (const int*)d_in[3];
    const float* W1   = (const float*)d_in[4];
    const float* b1   = (const float*)d_in[5];
    const float* W2   = (const float*)d_in[6];
    const float* b2   = (const float*)d_in[7];
    const float* W3   = (const float*)d_in[8];
    const float* b3   = (const float*)d_in[9];
    const float* W4   = (const float*)d_in[10];
    const float* b4   = (const float*)d_in[11];
    const float* a1   = (const float*)d_in[12];
    const float* a2   = (const float*)d_in[13];
    const float* a3   = (const float*)d_in[14];
    const float* Wlin = (const float*)d_in[15];
    const float* blin = (const float*)d_in[16];
    float* out = (float*)d_out;

    int n = in_sizes[0] / 8;
    int e = in_sizes[1];
    int G = out_size / 4;

    float *dinv, *xs, *ha, *hb, *z, *Wc, *bc;
    int *deg, *fill, *rowptr, *bsums, *col;
    cudaGetSymbolAddress((void**)&dinv,   g_dinv);
    cudaGetSymbolAddress((void**)&deg,    g_deg);
    cudaGetSymbolAddress((void**)&fill,   g_fill);
    cudaGetSymbolAddress((void**)&rowptr, g_rowptr);
    cudaGetSymbolAddress((void**)&bsums,  g_bsums);
    cudaGetSymbolAddress((void**)&col,    g_col);
    cudaGetSymbolAddress((void**)&xs,     g_xs);
    cudaGetSymbolAddress((void**)&ha,     g_ha);
    cudaGetSymbolAddress((void**)&hb,     g_hb);
    cudaGetSymbolAddress((void**)&z,      g_z);
    cudaGetSymbolAddress((void**)&Wc,     g_Wc);
    cudaGetSymbolAddress((void**)&bc,     g_bc);

    const int T = 256;
    int nscan = cdiv(n, SCAN_BLK);

    k_zero  <<<cdiv(n, T), T>>>(deg, fill, n);
    k_count <<<cdiv(e, T), T>>>(edst, deg, e);
    k_scan1 <<<nscan, SCAN_BLK>>>(deg, rowptr, bsums, dinv, n);
    k_scan2 <<<1, 256>>>(bsums, nscan);
    k_scan3 <<<cdiv(n + 1, T), T>>>(rowptr, bsums, x, dinv, xs, n, e);
    k_fillcsr<<<cdiv(e, T), T>>>(esrc, edst, rowptr, fill, col, e);
    k_head  <<<1, 256>>>(W4, b4, Wlin, blin, Wc, bc);

    // Layers 1-3 fused (agg + GEMM + PReLU + prescale)
    k_layer<8, 16> <<<cdiv(n, 128), T>>>(rowptr, col, xs, dinv, W1, b1, a1, ha, n);
    k_layer<16, 32><<<cdiv(n, 64),  T>>>(rowptr, col, ha, dinv, W2, b2, a2, hb, n);
    k_layer<32, 64><<<cdiv(n, 32),  T>>>(rowptr, col, hb, dinv, W3, b3, a3, ha, n);

    // Layer 4: aggregation only, then pooled composed head
    k_agg64<<<cdiv((long)n * 16, T), T>>>(rowptr, col, ha, dinv, z, n);
    k_pool <<<G, 256>>>(z, batch, Wc, bc, out, n);
}

// round 6
// speedup vs baseline: 1.2179x; 1.2179x over previous
#include <cuda_runtime.h>
#include <cstdint>

// ---------------------------------------------------------------------------
// BaseGCN round 5: warp-level fused agg+GEMM (no block barrier — shuffle GEMM),
// pre-scaled activations (no cnorm), fused CSR build, composed head.
//   hs = dinv * prelu(z @ W + b)
//   z[v] = dinv[v] * ( sum_{s in N(v)} hs[s] + hs[v] )
// ---------------------------------------------------------------------------

#define NMAX 100352
#define EMAX 1600000
#define SCAN_BLK 1024

__device__ float g_dinv[NMAX];
__device__ int   g_deg [NMAX];
__device__ int   g_fill[NMAX];
__device__ int   g_rowptr[NMAX + 1];
__device__ int   g_bsums[256];
__device__ int   g_col  [EMAX];
__device__ float g_xs[(size_t)NMAX * 8];    // dinv-scaled input features
__device__ float g_ha[(size_t)NMAX * 64];   // pre-scaled activations (ping)
__device__ float g_hb[(size_t)NMAX * 64];   // pre-scaled activations (pong)
__device__ float g_z [(size_t)NMAX * 64];   // layer-4 aggregate for pooling
__device__ float g_Wc[64 * 4];              // W4 @ Wlin
__device__ float g_bc[4];                   // b4 @ Wlin + blin

static inline int cdiv(long a, long b) { return (int)((a + b - 1) / b); }

// ---------------- CSR build ----------------
__global__ void k_zero(int* __restrict__ deg, int* __restrict__ fill, int n) {
    int i = blockIdx.x * blockDim.x + threadIdx.x;
    if (i < n) { deg[i] = 0; fill[i] = 0; }
}

__global__ void k_count(const int* __restrict__ dst, int* __restrict__ deg, int e) {
    int i = blockIdx.x * blockDim.x + threadIdx.x;
    if (i < e) atomicAdd(&deg[dst[i]], 1);
}

__global__ void k_scan1(const int* __restrict__ deg, int* __restrict__ rowptr,
                        int* __restrict__ bsums, float* __restrict__ dinv, int n) {
    __shared__ int sm[SCAN_BLK];
    int i = blockIdx.x * SCAN_BLK + threadIdx.x;
    int v = (i < n) ? deg[i] : 0;
    if (i < n) dinv[i] = rsqrtf((float)v + 1.0f);        // +1 self-loop
    sm[threadIdx.x] = v;
    __syncthreads();
#pragma unroll
    for (int off = 1; off < SCAN_BLK; off <<= 1) {
        int t = (threadIdx.x >= off) ? sm[threadIdx.x - off] : 0;
        __syncthreads();
        sm[threadIdx.x] += t;
        __syncthreads();
    }
    if (i < n) rowptr[i] = sm[threadIdx.x] - v;          // exclusive
    if (threadIdx.x == SCAN_BLK - 1) bsums[blockIdx.x] = sm[SCAN_BLK - 1];
}

__global__ void k_scan2(int* __restrict__ bsums, int nb) {
    __shared__ int sm[256];
    int v = (threadIdx.x < nb) ? bsums[threadIdx.x] : 0;
    sm[threadIdx.x] = v;
    __syncthreads();
#pragma unroll
    for (int off = 1; off < 256; off <<= 1) {
        int t = (threadIdx.x >= off) ? sm[threadIdx.x - off] : 0;
        __syncthreads();
        sm[threadIdx.x] += t;
        __syncthreads();
    }
    if (threadIdx.x < nb) bsums[threadIdx.x] = sm[threadIdx.x] - v;  // exclusive
}

__global__ void k_scan3(int* __restrict__ rowptr, const int* __restrict__ bsums,
                        const float* __restrict__ x, const float* __restrict__ dinv,
                        float* __restrict__ xs, int n, int e) {
    int i = blockIdx.x * blockDim.x + threadIdx.x;
    if (i >= n) { if (i == n) rowptr[n] = e; return; }
    rowptr[i] += bsums[i / SCAN_BLK];
    if (i == 0) rowptr[n] = e;
    float d = __ldg(&dinv[i]);
    const float4* x4 = reinterpret_cast<const float4*>(x) + (size_t)i * 2;
    float4* s4 = reinterpret_cast<float4*>(xs) + (size_t)i * 2;
    float4 a = __ldg(x4), b = __ldg(x4 + 1);
    a.x *= d; a.y *= d; a.z *= d; a.w *= d;
    b.x *= d; b.y *= d; b.z *= d; b.w *= d;
    s4[0] = a; s4[1] = b;
}

__global__ void k_fillcsr(const int* __restrict__ src, const int* __restrict__ dst,
                          const int* __restrict__ rowptr, int* __restrict__ fill,
                          int* __restrict__ col, int e) {
    int i = blockIdx.x * blockDim.x + threadIdx.x;
    if (i >= e) return;
    int d = dst[i];
    int pos = __ldg(&rowptr[d]) + atomicAdd(&fill[d], 1);
    col[pos] = src[i];
}

// ---------------- head precompose ----------------
__global__ void k_head(const float* __restrict__ W4, const float* __restrict__ b4,
                       const float* __restrict__ Wlin, const float* __restrict__ blin,
                       float* __restrict__ Wc, float* __restrict__ bc) {
    int t = threadIdx.x;
    int i = t >> 2, c = t & 3;
    float s = 0.f;
#pragma unroll 8
    for (int k = 0; k < 128; k++)
        s += __ldg(&W4[i * 128 + k]) * __ldg(&Wlin[k * 4 + c]);
    Wc[i * 4 + c] = s;
    if (i == 0) {
        float b = __ldg(&blin[c]);
#pragma unroll 8
        for (int k = 0; k < 128; k++)
            b += __ldg(&b4[k]) * __ldg(&Wlin[k * 4 + c]);
        bc[c] = b;
    }
}

// ---------------- warp-fused agg + shuffle GEMM + PReLU + prescale ----------
// TPE = FIN/4 lanes per node (within one warp). Gather -> registers,
// GEMM via __shfl_sync broadcasts, write FOUT row directly. No block barrier.
template<int FIN, int FOUT>
__global__ void __launch_bounds__(256)
k_wlayer(const int* __restrict__ rowptr, const int* __restrict__ col,
         const float* __restrict__ hs, const float* __restrict__ dinv,
         const float* __restrict__ W, const float* __restrict__ bias,
         const float* __restrict__ aP, float* __restrict__ out, int n) {
    constexpr int TPE = FIN / 4;
    constexpr int NPB = 256 / TPE;
    constexpr int CPL = FOUT / TPE;           // columns per lane (= 8 for all layers)
    static_assert(CPL == 8, "expect 8 cols/lane");

    __shared__ float Ws[FIN * FOUT];
    __shared__ float bs[FOUT];
    for (int i = threadIdx.x; i < FIN * FOUT; i += 256) Ws[i] = __ldg(&W[i]);
    if (threadIdx.x < FOUT) bs[threadIdx.x] = __ldg(&bias[threadIdx.x]);
    float a = __ldg(aP);
    __syncthreads();                           // weights only; before any gather

    int group = threadIdx.x / TPE;
    int lane  = threadIdx.x % TPE;
    int node  = blockIdx.x * NPB + group;
    bool live = (node < n);
    int node_c = live ? node : (n - 1);        // clamp: keep all lanes active for shfl

    int beg = __ldg(&rowptr[node_c]);
    int end = __ldg(&rowptr[node_c + 1]);
    const float4* h4 = reinterpret_cast<const float4*>(hs);
    float4 acc = __ldg(h4 + (size_t)node_c * TPE + lane);   // self (pre-scaled)
    int p = beg;
    for (; p + 4 <= end; p += 4) {
        int s0 = __ldg(&col[p + 0]);
        int s1 = __ldg(&col[p + 1]);
        int s2 = __ldg(&col[p + 2]);
        int s3 = __ldg(&col[p + 3]);
        float4 v0 = __ldg(h4 + (size_t)s0 * TPE + lane);
        float4 v1 = __ldg(h4 + (size_t)s1 * TPE + lane);
        float4 v2 = __ldg(h4 + (size_t)s2 * TPE + lane);
        float4 v3 = __ldg(h4 + (size_t)s3 * TPE + lane);
        acc.x += v0.x + v1.x + v2.x + v3.x;
        acc.y += v0.y + v1.y + v2.y + v3.y;
        acc.z += v0.z + v1.z + v2.z + v3.z;
        acc.w += v0.w + v1.w + v2.w + v3.w;
    }
    for (; p < end; p++) {
        int s = __ldg(&col[p]);
        float4 v = __ldg(h4 + (size_t)s * TPE + lane);
        acc.x += v.x; acc.y += v.y; acc.z += v.z; acc.w += v.w;
    }
    float dn = __ldg(&dinv[node_c]);
    float za[4] = {acc.x * dn, acc.y * dn, acc.z * dn, acc.w * dn};

    // shuffle GEMM: lane computes columns [lane*8, lane*8+8)
    int lane32 = threadIdx.x & 31;
    int base   = lane32 & ~(TPE - 1);          // group's first lane in warp
    int c0 = lane * CPL;
    float4 o0 = *reinterpret_cast<const float4*>(&bs[c0]);
    float4 o1 = *reinterpret_cast<const float4*>(&bs[c0 + 4]);
#pragma unroll
    for (int k4 = 0; k4 < TPE; k4++) {
#pragma unroll
        for (int j = 0; j < 4; j++) {
            float zk = __shfl_sync(0xffffffffu, za[j], base + k4);
            int k = k4 * 4 + j;
            float4 wa = *reinterpret_cast<const float4*>(&Ws[k * FOUT + c0]);
            float4 wb = *reinterpret_cast<const float4*>(&Ws[k * FOUT + c0 + 4]);
            o0.x += zk * wa.x; o0.y += zk * wa.y; o0.z += zk * wa.z; o0.w += zk * wa.w;
            o1.x += zk * wb.x; o1.y += zk * wb.y; o1.z += zk * wb.z; o1.w += zk * wb.w;
        }
    }
    if (live) {
        o0.x = o0.x >= 0.f ? o0.x : a * o0.x;
        o0.y = o0.y >= 0.f ? o0.y : a * o0.y;
        o0.z = o0.z >= 0.f ? o0.z : a * o0.z;
        o0.w = o0.w >= 0.f ? o0.w : a * o0.w;
        o1.x = o1.x >= 0.f ? o1.x : a * o1.x;
        o1.y = o1.y >= 0.f ? o1.y : a * o1.y;
        o1.z = o1.z >= 0.f ? o1.z : a * o1.z;
        o1.w = o1.w >= 0.f ? o1.w : a * o1.w;
        o0.x *= dn; o0.y *= dn; o0.z *= dn; o0.w *= dn;
        o1.x *= dn; o1.y *= dn; o1.z *= dn; o1.w *= dn;
        float4* orow = reinterpret_cast<float4*>(out + (size_t)node * FOUT + c0);
        orow[0] = o0;
        orow[1] = o1;
    }
}

// ---------------- layer-4 aggregation only (true z, 64-wide) ----------------
__global__ void __launch_bounds__(256)
k_agg64(const int* __restrict__ rowptr, const int* __restrict__ col,
        const float* __restrict__ hs, const float* __restrict__ dinv,
        float* __restrict__ z, int n) {
    constexpr int TPE = 16;
    long gid = (long)blockIdx.x * blockDim.x + threadIdx.x;
    int node = (int)(gid / TPE);
    int lane = (int)(gid % TPE);
    if (node >= n) return;

    int beg = __ldg(&rowptr[node]);
    int end = __ldg(&rowptr[node + 1]);
    const float4* h4 = reinterpret_cast<const float4*>(hs);
    float4 acc = __ldg(h4 + (size_t)node * TPE + lane);
    int p = beg;
    for (; p + 4 <= end; p += 4) {
        int s0 = __ldg(&col[p + 0]);
        int s1 = __ldg(&col[p + 1]);
        int s2 = __ldg(&col[p + 2]);
        int s3 = __ldg(&col[p + 3]);
        float4 v0 = __ldg(h4 + (size_t)s0 * TPE + lane);
        float4 v1 = __ldg(h4 + (size_t)s1 * TPE + lane);
        float4 v2 = __ldg(h4 + (size_t)s2 * TPE + lane);
        float4 v3 = __ldg(h4 + (size_t)s3 * TPE + lane);
        acc.x += v0.x + v1.x + v2.x + v3.x;
        acc.y += v0.y + v1.y + v2.y + v3.y;
        acc.z += v0.z + v1.z + v2.z + v3.z;
        acc.w += v0.w + v1.w + v2.w + v3.w;
    }
    for (; p < end; p++) {
        int s = __ldg(&col[p]);
        float4 v = __ldg(h4 + (size_t)s * TPE + lane);
        acc.x += v.x; acc.y += v.y; acc.z += v.z; acc.w += v.w;
    }
    float d = __ldg(&dinv[node]);
    acc.x *= d; acc.y *= d; acc.z *= d; acc.w *= d;
    reinterpret_cast<float4*>(z)[(size_t)node * TPE + lane] = acc;
}

// ---------------- pool (64-wide mean per graph) + composed head -------------
__device__ __forceinline__ int lower_bound_i(const int* b, int n, int v) {
    int lo = 0, hi = n;
    while (lo < hi) {
        int m = (lo + hi) >> 1;
        if (__ldg(&b[m]) < v) lo = m + 1; else hi = m;
    }
    return lo;
}

__global__ void k_pool(const float* __restrict__ z, const int* __restrict__ batch,
                       const float* __restrict__ Wc, const float* __restrict__ bc,
                       float* __restrict__ out, int n) {
    const int F = 64;
    int g = blockIdx.x;
    int start = lower_bound_i(batch, n, g);
    int end   = lower_bound_i(batch, n, g + 1);

    int c   = threadIdx.x & (F - 1);
    int sub = threadIdx.x >> 6;
    float acc = 0.f;
    for (int r = start + sub; r < end; r += 4)
        acc += __ldg(&z[(size_t)r * F + c]);

    __shared__ float sm[256];
    __shared__ float pooled[F];
    sm[threadIdx.x] = acc;
    __syncthreads();
    if (threadIdx.x < F) {
        int cnt = end - start;
        float denom = (float)(cnt > 1 ? cnt : 1);
        pooled[threadIdx.x] = (sm[threadIdx.x] + sm[threadIdx.x + 64] +
                               sm[threadIdx.x + 128] + sm[threadIdx.x + 192]) / denom;
    }
    __syncthreads();
    if (threadIdx.x < 4) {
        float s = __ldg(&bc[threadIdx.x]);
#pragma unroll 8
        for (int f = 0; f < F; f++)
            s += pooled[f] * __ldg(&Wc[f * 4 + threadIdx.x]);
        out[g * 4 + threadIdx.x] = s;
    }
}

// ---------------------------------------------------------------------------
extern "C" void kernel_launch(void* const* d_in, const int* in_sizes, int n_in,
                              void* d_out, int out_size) {
    const float* x    = (const float*)d_in[0];
    const int* esrc   = (const int*)d_in[1];
    const int* edst   = (const int*)d_in[2];
    const int* batch  = (const int*)d_in[3];
    const float* W1   = (const float*)d_in[4];
    const float* b1   = (const float*)d_in[5];
    const float* W2   = (const float*)d_in[6];
    const float* b2   = (const float*)d_in[7];
    const float* W3   = (const float*)d_in[8];
    const float* b3   = (const float*)d_in[9];
    const float* W4   = (const float*)d_in[10];
    const float* b4   = (const float*)d_in[11];
    const float* a1   = (const float*)d_in[12];
    const float* a2   = (const float*)d_in[13];
    const float* a3   = (const float*)d_in[14];
    const float* Wlin = (const float*)d_in[15];
    const float* blin = (const float*)d_in[16];
    float* out = (float*)d_out;

    int n = in_sizes[0] / 8;
    int e = in_sizes[1];
    int G = out_size / 4;

    float *dinv, *xs, *ha, *hb, *z, *Wc, *bc;
    int *deg, *fill, *rowptr, *bsums, *col;
    cudaGetSymbolAddress((void**)&dinv,   g_dinv);
    cudaGetSymbolAddress((void**)&deg,    g_deg);
    cudaGetSymbolAddress((void**)&fill,   g_fill);
    cudaGetSymbolAddress((void**)&rowptr, g_rowptr);
    cudaGetSymbolAddress((void**)&bsums,  g_bsums);
    cudaGetSymbolAddress((void**)&col,    g_col);
    cudaGetSymbolAddress((void**)&xs,     g_xs);
    cudaGetSymbolAddress((void**)&ha,     g_ha);
    cudaGetSymbolAddress((void**)&hb,     g_hb);
    cudaGetSymbolAddress((void**)&z,      g_z);
    cudaGetSymbolAddress((void**)&Wc,     g_Wc);
    cudaGetSymbolAddress((void**)&bc,     g_bc);

    const int T = 256;
    int nscan = cdiv(n, SCAN_BLK);

    k_zero  <<<cdiv(n, T), T>>>(deg, fill, n);
    k_count <<<cdiv(e, T), T>>>(edst, deg, e);
    k_scan1 <<<nscan, SCAN_BLK>>>(deg, rowptr, bsums, dinv, n);
    k_scan2 <<<1, 256>>>(bsums, nscan);
    k_scan3 <<<cdiv(n + 1, T), T>>>(rowptr, bsums, x, dinv, xs, n, e);
    k_fillcsr<<<cdiv(e, T), T>>>(esrc, edst, rowptr, fill, col, e);
    k_head  <<<1, 256>>>(W4, b4, Wlin, blin, Wc, bc);

    // Layers 1-3: warp-fused agg + shuffle GEMM
    k_wlayer<8, 16> <<<cdiv(n, 128), T>>>(rowptr, col, xs, dinv, W1, b1, a1, ha, n);
    k_wlayer<16, 32><<<cdiv(n, 64),  T>>>(rowptr, col, ha, dinv, W2, b2, a2, hb, n);
    k_wlayer<32, 64><<<cdiv(n, 32),  T>>>(rowptr, col, hb, dinv, W3, b3, a3, ha, n);

    // Layer 4: aggregation only, then pooled composed head
    k_agg64<<<cdiv((long)n * 16, T), T>>>(rowptr, col, ha, dinv, z, n);
    k_pool <<<G, 256>>>(z, batch, Wc, bc, out, n);
}

// round 9
// speedup vs baseline: 1.4016x; 1.1508x over previous
#include <cuda_runtime.h>
#include <cstdint>

// ---------------------------------------------------------------------------
// BaseGCN round 6: project hs3 through the composed head (64->4) BEFORE the
// layer-4 aggregation: gathers shrink 256B -> 16B per edge. Layer-4 agg +
// pool + head fused into one kernel with smem graph accumulators.
//   hs = dinv * prelu(z @ W + b)         (pre-scaled activations)
//   hp = hs3 @ Wc                        (4-wide projected activations)
//   out_g = (sum_{v in g} dinv_v*(sum_s hp_s + hp_v)) / cnt_g + bc
// ---------------------------------------------------------------------------

#define NMAX 100352
#define EMAX 1600000
#define SCAN_BLK 1024

__device__ float g_dinv[NMAX];
__device__ int   g_deg [NMAX];
__device__ int   g_fill[NMAX];
__device__ int   g_rowptr[NMAX + 1];
__device__ int   g_bsums[256];
__device__ int   g_col  [EMAX];
__device__ float g_xs[(size_t)NMAX * 8];    // dinv-scaled input features
__device__ float g_ha[(size_t)NMAX * 64];   // pre-scaled activations (ping)
__device__ float g_hb[(size_t)NMAX * 64];   // pre-scaled activations (pong)
__device__ float g_hp[(size_t)NMAX * 4];    // projected activations (hs3 @ Wc)
__device__ float g_accum[64 * 4];           // per-graph accumulators
__device__ float g_Wc[64 * 4];              // W4 @ Wlin
__device__ float g_bc[4];                   // b4 @ Wlin + blin

static inline int cdiv(long a, long b) { return (int)((a + b - 1) / b); }

// ---------------- CSR build ----------------
__global__ void k_zero(int* __restrict__ deg, int* __restrict__ fill,
                       float* __restrict__ accum, int n) {
    int i = blockIdx.x * blockDim.x + threadIdx.x;
    if (i < n) { deg[i] = 0; fill[i] = 0; }
    if (i < 256) accum[i] = 0.f;
}

__global__ void k_count(const int* __restrict__ dst, int* __restrict__ deg, int e) {
    int i = blockIdx.x * blockDim.x + threadIdx.x;
    if (i < e) atomicAdd(&deg[dst[i]], 1);
}

__global__ void k_scan1(const int* __restrict__ deg, int* __restrict__ rowptr,
                        int* __restrict__ bsums, float* __restrict__ dinv, int n) {
    __shared__ int sm[SCAN_BLK];
    int i = blockIdx.x * SCAN_BLK + threadIdx.x;
    int v = (i < n) ? deg[i] : 0;
    if (i < n) dinv[i] = rsqrtf((float)v + 1.0f);        // +1 self-loop
    sm[threadIdx.x] = v;
    __syncthreads();
#pragma unroll
    for (int off = 1; off < SCAN_BLK; off <<= 1) {
        int t = (threadIdx.x >= off) ? sm[threadIdx.x - off] : 0;
        __syncthreads();
        sm[threadIdx.x] += t;
        __syncthreads();
    }
    if (i < n) rowptr[i] = sm[threadIdx.x] - v;          // exclusive
    if (threadIdx.x == SCAN_BLK - 1) bsums[blockIdx.x] = sm[SCAN_BLK - 1];
}

__global__ void k_scan2(int* __restrict__ bsums, int nb) {
    __shared__ int sm[256];
    int v = (threadIdx.x < nb) ? bsums[threadIdx.x] : 0;
    sm[threadIdx.x] = v;
    __syncthreads();
#pragma unroll
    for (int off = 1; off < 256; off <<= 1) {
        int t = (threadIdx.x >= off) ? sm[threadIdx.x - off] : 0;
        __syncthreads();
        sm[threadIdx.x] += t;
        __syncthreads();
    }
    if (threadIdx.x < nb) bsums[threadIdx.x] = sm[threadIdx.x] - v;  // exclusive
}

__global__ void k_scan3(int* __restrict__ rowptr, const int* __restrict__ bsums,
                        const float* __restrict__ x, const float* __restrict__ dinv,
                        float* __restrict__ xs, int n, int e) {
    int i = blockIdx.x * blockDim.x + threadIdx.x;
    if (i >= n) { if (i == n) rowptr[n] = e; return; }
    rowptr[i] += bsums[i / SCAN_BLK];
    if (i == 0) rowptr[n] = e;
    float d = __ldg(&dinv[i]);
    const float4* x4 = reinterpret_cast<const float4*>(x) + (size_t)i * 2;
    float4* s4 = reinterpret_cast<float4*>(xs) + (size_t)i * 2;
    float4 a = __ldg(x4), b = __ldg(x4 + 1);
    a.x *= d; a.y *= d; a.z *= d; a.w *= d;
    b.x *= d; b.y *= d; b.z *= d; b.w *= d;
    s4[0] = a; s4[1] = b;
}

__global__ void k_fillcsr(const int* __restrict__ src, const int* __restrict__ dst,
                          const int* __restrict__ rowptr, int* __restrict__ fill,
                          int* __restrict__ col, int e) {
    int i = blockIdx.x * blockDim.x + threadIdx.x;
    if (i >= e) return;
    int d = dst[i];
    int pos = __ldg(&rowptr[d]) + atomicAdd(&fill[d], 1);
    col[pos] = src[i];
}

// ---------------- head precompose ----------------
__global__ void k_head(const float* __restrict__ W4, const float* __restrict__ b4,
                       const float* __restrict__ Wlin, const float* __restrict__ blin,
                       float* __restrict__ Wc, float* __restrict__ bc) {
    int t = threadIdx.x;
    int i = t >> 2, c = t & 3;
    float s = 0.f;
#pragma unroll 8
    for (int k = 0; k < 128; k++)
        s += __ldg(&W4[i * 128 + k]) * __ldg(&Wlin[k * 4 + c]);
    Wc[i * 4 + c] = s;
    if (i == 0) {
        float b = __ldg(&blin[c]);
#pragma unroll 8
        for (int k = 0; k < 128; k++)
            b += __ldg(&b4[k]) * __ldg(&Wlin[k * 4 + c]);
        bc[c] = b;
    }
}

// ---------------- warp-fused agg + shuffle GEMM + PReLU + prescale ----------
// PROJ: additionally emit hp = hs_out @ Wc (4-wide) via intra-group reduce.
template<int FIN, int FOUT, bool PROJ>
__global__ void __launch_bounds__(256)
k_wlayer(const int* __restrict__ rowptr, const int* __restrict__ col,
         const float* __restrict__ hs, const float* __restrict__ dinv,
         const float* __restrict__ W, const float* __restrict__ bias,
         const float* __restrict__ aP, float* __restrict__ out,
         const float* __restrict__ Wc, float* __restrict__ hp, int n) {
    constexpr int TPE = FIN / 4;
    constexpr int NPB = 256 / TPE;
    constexpr int CPL = FOUT / TPE;           // columns per lane (= 8)
    static_assert(CPL == 8, "expect 8 cols/lane");

    __shared__ float Ws[FIN * FOUT];
    __shared__ float bs[FOUT];
    __shared__ float Wcs[PROJ ? FOUT * 4 : 1];
    for (int i = threadIdx.x; i < FIN * FOUT; i += 256) Ws[i] = __ldg(&W[i]);
    if (threadIdx.x < FOUT) bs[threadIdx.x] = __ldg(&bias[threadIdx.x]);
    if (PROJ) {
        for (int i = threadIdx.x; i < FOUT * 4; i += 256) Wcs[i] = __ldg(&Wc[i]);
    }
    float a = __ldg(aP);
    __syncthreads();

    int group = threadIdx.x / TPE;
    int lane  = threadIdx.x % TPE;
    int node  = blockIdx.x * NPB + group;
    bool live = (node < n);
    int node_c = live ? node : (n - 1);        // clamp: keep lanes active for shfl

    int beg = __ldg(&rowptr[node_c]);
    int end = __ldg(&rowptr[node_c + 1]);
    const float4* h4 = reinterpret_cast<const float4*>(hs);
    float4 acc = __ldg(h4 + (size_t)node_c * TPE + lane);   // self (pre-scaled)
    int p = beg;
    for (; p + 4 <= end; p += 4) {
        int s0 = __ldg(&col[p + 0]);
        int s1 = __ldg(&col[p + 1]);
        int s2 = __ldg(&col[p + 2]);
        int s3 = __ldg(&col[p + 3]);
        float4 v0 = __ldg(h4 + (size_t)s0 * TPE + lane);
        float4 v1 = __ldg(h4 + (size_t)s1 * TPE + lane);
        float4 v2 = __ldg(h4 + (size_t)s2 * TPE + lane);
        float4 v3 = __ldg(h4 + (size_t)s3 * TPE + lane);
        acc.x += v0.x + v1.x + v2.x + v3.x;
        acc.y += v0.y + v1.y + v2.y + v3.y;
        acc.z += v0.z + v1.z + v2.z + v3.z;
        acc.w += v0.w + v1.w + v2.w + v3.w;
    }
    for (; p < end; p++) {
        int s = __ldg(&col[p]);
        float4 v = __ldg(h4 + (size_t)s * TPE + lane);
        acc.x += v.x; acc.y += v.y; acc.z += v.z; acc.w += v.w;
    }
    float dn = __ldg(&dinv[node_c]);
    float za[4] = {acc.x * dn, acc.y * dn, acc.z * dn, acc.w * dn};

    // shuffle GEMM: lane computes columns [lane*8, lane*8+8)
    int lane32 = threadIdx.x & 31;
    int base   = lane32 & ~(TPE - 1);
    int c0 = lane * CPL;
    float4 o0 = *reinterpret_cast<const float4*>(&bs[c0]);
    float4 o1 = *reinterpret_cast<const float4*>(&bs[c0 + 4]);
#pragma unroll
    for (int k4 = 0; k4 < TPE; k4++) {
#pragma unroll
        for (int j = 0; j < 4; j++) {
            float zk = __shfl_sync(0xffffffffu, za[j], base + k4);
            int k = k4 * 4 + j;
            float4 wa = *reinterpret_cast<const float4*>(&Ws[k * FOUT + c0]);
            float4 wb = *reinterpret_cast<const float4*>(&Ws[k * FOUT + c0 + 4]);
            o0.x += zk * wa.x; o0.y += zk * wa.y; o0.z += zk * wa.z; o0.w += zk * wa.w;
            o1.x += zk * wb.x; o1.y += zk * wb.y; o1.z += zk * wb.z; o1.w += zk * wb.w;
        }
    }
    // PReLU + prescale (compute on all lanes; only live lanes store)
    o0.x = o0.x >= 0.f ? o0.x : a * o0.x;
    o0.y = o0.y >= 0.f ? o0.y : a * o0.y;
    o0.z = o0.z >= 0.f ? o0.z : a * o0.z;
    o0.w = o0.w >= 0.f ? o0.w : a * o0.w;
    o1.x = o1.x >= 0.f ? o1.x : a * o1.x;
    o1.y = o1.y >= 0.f ? o1.y : a * o1.y;
    o1.z = o1.z >= 0.f ? o1.z : a * o1.z;
    o1.w = o1.w >= 0.f ? o1.w : a * o1.w;
    o0.x *= dn; o0.y *= dn; o0.z *= dn; o0.w *= dn;
    o1.x *= dn; o1.y *= dn; o1.z *= dn; o1.w *= dn;
    if (live) {
        float4* orow = reinterpret_cast<float4*>(out + (size_t)node * FOUT + c0);
        orow[0] = o0;
        orow[1] = o1;
    }

    if (PROJ) {
        // partial projection: this lane's 8 columns through Wc (FOUTx4)
        float pj[4] = {0.f, 0.f, 0.f, 0.f};
        const float* hv = &o0.x;               // o0,o1 contiguous? not guaranteed -> use array
        float hvals[8] = {o0.x, o0.y, o0.z, o0.w, o1.x, o1.y, o1.z, o1.w};
#pragma unroll
        for (int j = 0; j < 8; j++) {
            float4 w = *reinterpret_cast<const float4*>(&Wcs[(c0 + j) * 4]);
            pj[0] += hvals[j] * w.x; pj[1] += hvals[j] * w.y;
            pj[2] += hvals[j] * w.z; pj[3] += hvals[j] * w.w;
        }
        (void)hv;
        // reduce across the TPE(=8) lanes of this group (contiguous in warp)
#pragma unroll
        for (int off = TPE / 2; off > 0; off >>= 1) {
#pragma unroll
            for (int j = 0; j < 4; j++)
                pj[j] += __shfl_xor_sync(0xffffffffu, pj[j], off);
        }
        if (live && lane == 0) {
            float4 r = {pj[0], pj[1], pj[2], pj[3]};
            reinterpret_cast<float4*>(hp)[node] = r;
        }
    }
}

// ---------------- fused layer-4 agg (4-wide) + graph pooling ----------------
// per node: q = dinv_v * (hp_v + sum_edges hp_src); accum[batch[v]] += q
__global__ void __launch_bounds__(256)
k_z4pool(const int* __restrict__ rowptr, const int* __restrict__ col,
         const float* __restrict__ hp, const float* __restrict__ dinv,
         const int* __restrict__ batch, float* __restrict__ accum, int n) {
    __shared__ float acc_s[64 * 4];
    if (threadIdx.x < 256) acc_s[threadIdx.x] = 0.f;
    __syncthreads();

    int node = blockIdx.x * blockDim.x + threadIdx.x;
    if (node < n) {
        const float4* hp4 = reinterpret_cast<const float4*>(hp);
        float4 acc = __ldg(hp4 + node);        // self
        int beg = __ldg(&rowptr[node]);
        int end = __ldg(&rowptr[node + 1]);
        int p = beg;
        for (; p + 4 <= end; p += 4) {
            int s0 = __ldg(&col[p + 0]);
            int s1 = __ldg(&col[p + 1]);
            int s2 = __ldg(&col[p + 2]);
            int s3 = __ldg(&col[p + 3]);
            float4 v0 = __ldg(hp4 + s0);
            float4 v1 = __ldg(hp4 + s1);
            float4 v2 = __ldg(hp4 + s2);
            float4 v3 = __ldg(hp4 + s3);
            acc.x += v0.x + v1.x + v2.x + v3.x;
            acc.y += v0.y + v1.y + v2.y + v3.y;
            acc.z += v0.z + v1.z + v2.z + v3.z;
            acc.w += v0.w + v1.w + v2.w + v3.w;
        }
        for (; p < end; p++) {
            int s = __ldg(&col[p]);
            float4 v = __ldg(hp4 + s);
            acc.x += v.x; acc.y += v.y; acc.z += v.z; acc.w += v.w;
        }
        float d = __ldg(&dinv[node]);
        int g = __ldg(&batch[node]);
        atomicAdd(&acc_s[g * 4 + 0], acc.x * d);
        atomicAdd(&acc_s[g * 4 + 1], acc.y * d);
        atomicAdd(&acc_s[g * 4 + 2], acc.z * d);
        atomicAdd(&acc_s[g * 4 + 3], acc.w * d);
    }
    __syncthreads();
    if (threadIdx.x < 256) {
        float v = acc_s[threadIdx.x];
        if (v != 0.f) atomicAdd(&accum[threadIdx.x], v);
    }
}

// ---------------- finish: divide by counts, add bc ----------------
__device__ __forceinline__ int lower_bound_i(const int* b, int n, int v) {
    int lo = 0, hi = n;
    while (lo < hi) {
        int m = (lo + hi) >> 1;
        if (__ldg(&b[m]) < v) lo = m + 1; else hi = m;
    }
    return lo;
}

__global__ void k_finish(const float* __restrict__ accum, const int* __restrict__ batch,
                         const float* __restrict__ bc, float* __restrict__ out,
                         int n, int G) {
    int t = threadIdx.x;               // 256 threads: g = t/4, c = t%4
    int g = t >> 2, c = t & 3;
    if (g >= G) return;
    int start = lower_bound_i(batch, n, g);
    int end   = lower_bound_i(batch, n, g + 1);
    int cnt = end - start;
    float denom = (float)(cnt > 1 ? cnt : 1);
    out[g * 4 + c] = accum[g * 4 + c] / denom + __ldg(&bc[c]);
}

// ---------------------------------------------------------------------------
extern "C" void kernel_launch(void* const* d_in, const int* in_sizes, int n_in,
                              void* d_out, int out_size) {
    const float* x    = (const float*)d_in[0];
    const int* esrc   = (const int*)d_in[1];
    const int* edst   = (const int*)d_in[2];
    const int* batch  = (const int*)d_in[3];
    const float* W1   = (const float*)d_in[4];
    const float* b1   = (const float*)d_in[5];
    const float* W2   = (const float*)d_in[6];
    const float* b2   = (const float*)d_in[7];
    const float* W3   = (const float*)d_in[8];
    const float* b3   = (const float*)d_in[9];
    const float* W4   = (const float*)d_in[10];
    const float* b4   = (const float*)d_in[11];
    const float* a1   = (const float*)d_in[12];
    const float* a2   = (const float*)d_in[13];
    const float* a3   = (const float*)d_in[14];
    const float* Wlin = (const float*)d_in[15];
    const float* blin = (const float*)d_in[16];
    float* out = (float*)d_out;

    int n = in_sizes[0] / 8;
    int e = in_sizes[1];
    int G = out_size / 4;

    float *dinv, *xs, *ha, *hb, *hp, *accum, *Wc, *bc;
    int *deg, *fill, *rowptr, *bsums, *col;
    cudaGetSymbolAddress((void**)&dinv,   g_dinv);
    cudaGetSymbolAddress((void**)&deg,    g_deg);
    cudaGetSymbolAddress((void**)&fill,   g_fill);
    cudaGetSymbolAddress((void**)&rowptr, g_rowptr);
    cudaGetSymbolAddress((void**)&bsums,  g_bsums);
    cudaGetSymbolAddress((void**)&col,    g_col);
    cudaGetSymbolAddress((void**)&xs,     g_xs);
    cudaGetSymbolAddress((void**)&ha,     g_ha);
    cudaGetSymbolAddress((void**)&hb,     g_hb);
    cudaGetSymbolAddress((void**)&hp,     g_hp);
    cudaGetSymbolAddress((void**)&accum,  g_accum);
    cudaGetSymbolAddress((void**)&Wc,     g_Wc);
    cudaGetSymbolAddress((void**)&bc,     g_bc);

    const int T = 256;
    int nscan = cdiv(n, SCAN_BLK);

    k_zero  <<<cdiv(n, T), T>>>(deg, fill, accum, n);
    k_count <<<cdiv(e, T), T>>>(edst, deg, e);
    k_scan1 <<<nscan, SCAN_BLK>>>(deg, rowptr, bsums, dinv, n);
    k_scan2 <<<1, 256>>>(bsums, nscan);
    k_scan3 <<<cdiv(n + 1, T), T>>>(rowptr, bsums, x, dinv, xs, n, e);
    k_fillcsr<<<cdiv(e, T), T>>>(esrc, edst, rowptr, fill, col, e);
    k_head  <<<1, 256>>>(W4, b4, Wlin, blin, Wc, bc);

    // Layers 1-3: warp-fused agg + shuffle GEMM (layer 3 also projects -> hp)
    k_wlayer<8, 16, false><<<cdiv(n, 128), T>>>(rowptr, col, xs, dinv, W1, b1, a1, ha, nullptr, nullptr, n);
    k_wlayer<16, 32, false><<<cdiv(n, 64), T>>>(rowptr, col, ha, dinv, W2, b2, a2, hb, nullptr, nullptr, n);
    k_wlayer<32, 64, true> <<<cdiv(n, 32), T>>>(rowptr, col, hb, dinv, W3, b3, a3, ha, Wc, hp, n);

    // Layer 4 (4-wide) + pooling fused; then finish
    k_z4pool<<<cdiv(n, T), T>>>(rowptr, col, hp, dinv, batch, accum, n);
    k_finish<<<1, 256>>>(accum, batch, bc, out, n, G);
}

// round 11
// speedup vs baseline: 1.4638x; 1.0444x over previous
#include <cuda_runtime.h>
#include <cstdint>

// ---------------------------------------------------------------------------
// BaseGCN round 7 (re-run; previous attempt hit an infra failure):
// degree-sorted node permutation (counting sort, built once) so each warp
// processes equal-degree nodes -> no intra-warp straggler.
// Keeps: warp-fused agg+shuffle GEMM, pre-scaled activations, projected
// layer-4 (64->4) + fused pooling, composed head.
// ---------------------------------------------------------------------------

#define NMAX 100352
#define EMAX 1600000
#define SCAN_BLK 1024

__device__ float g_dinv[NMAX];
__device__ int   g_deg [NMAX];
__device__ int   g_fill[NMAX];
__device__ int   g_rowptr[NMAX + 1];
__device__ int   g_bsums[256];
__device__ int   g_hist[256];
__device__ int   g_hbase[256];
__device__ int   g_hfill[256];
__device__ int   g_perm[NMAX];
__device__ int   g_col  [EMAX];
__device__ float g_xs[(size_t)NMAX * 8];
__device__ float g_ha[(size_t)NMAX * 64];
__device__ float g_hb[(size_t)NMAX * 64];
__device__ float g_hp[(size_t)NMAX * 4];
__device__ float g_accum[64 * 4];
__device__ float g_Wc[64 * 4];
__device__ float g_bc[4];

static inline int cdiv(long a, long b) { return (int)((a + b - 1) / b); }

// ---------------- init ----------------
__global__ void k_zero(int* __restrict__ deg, int* __restrict__ fill,
                       int* __restrict__ hist, int* __restrict__ hfill,
                       float* __restrict__ accum, int n) {
    int i = blockIdx.x * blockDim.x + threadIdx.x;
    if (i < n) { deg[i] = 0; fill[i] = 0; }
    if (i < 256) { hist[i] = 0; hfill[i] = 0; accum[i] = 0.f; }
}

__global__ void k_count(const int* __restrict__ dst, int* __restrict__ deg, int e) {
    int i = blockIdx.x * blockDim.x + threadIdx.x;
    if (i < e) atomicAdd(&deg[dst[i]], 1);
}

// scan deg -> rowptr (block-local), bsums; dinv; block-aggregated degree hist.
__global__ void k_scan1(const int* __restrict__ deg, int* __restrict__ rowptr,
                        int* __restrict__ bsums, float* __restrict__ dinv,
                        int* __restrict__ hist, int n) {
    __shared__ int sm[SCAN_BLK];
    __shared__ int hist_s[256];
    if (threadIdx.x < 256) hist_s[threadIdx.x] = 0;
    int i = blockIdx.x * SCAN_BLK + threadIdx.x;
    int v = (i < n) ? deg[i] : 0;
    if (i < n) dinv[i] = rsqrtf((float)v + 1.0f);
    sm[threadIdx.x] = v;
    __syncthreads();
    if (i < n) atomicAdd(&hist_s[v < 255 ? v : 255], 1);
#pragma unroll
    for (int off = 1; off < SCAN_BLK; off <<= 1) {
        int t = (threadIdx.x >= off) ? sm[threadIdx.x - off] : 0;
        __syncthreads();
        sm[threadIdx.x] += t;
        __syncthreads();
    }
    if (i < n) rowptr[i] = sm[threadIdx.x] - v;
    if (threadIdx.x == SCAN_BLK - 1) bsums[blockIdx.x] = sm[SCAN_BLK - 1];
    __syncthreads();
    if (threadIdx.x < 256 && hist_s[threadIdx.x])
        atomicAdd(&hist[threadIdx.x], hist_s[threadIdx.x]);
}

// combined: exclusive scan of bsums (nb entries) and of hist (256 entries)
__global__ void k_scan2(int* __restrict__ bsums, const int* __restrict__ hist,
                        int* __restrict__ hbase, int nb) {
    __shared__ int sm[256];
    int v = (threadIdx.x < nb) ? bsums[threadIdx.x] : 0;
    sm[threadIdx.x] = v;
    __syncthreads();
#pragma unroll
    for (int off = 1; off < 256; off <<= 1) {
        int t = (threadIdx.x >= off) ? sm[threadIdx.x - off] : 0;
        __syncthreads();
        sm[threadIdx.x] += t;
        __syncthreads();
    }
    if (threadIdx.x < nb) bsums[threadIdx.x] = sm[threadIdx.x] - v;
    __syncthreads();
    int h = hist[threadIdx.x];
    sm[threadIdx.x] = h;
    __syncthreads();
#pragma unroll
    for (int off = 1; off < 256; off <<= 1) {
        int t = (threadIdx.x >= off) ? sm[threadIdx.x - off] : 0;
        __syncthreads();
        sm[threadIdx.x] += t;
        __syncthreads();
    }
    hbase[threadIdx.x] = sm[threadIdx.x] - h;
}

__global__ void k_scan3(int* __restrict__ rowptr, const int* __restrict__ bsums,
                        const float* __restrict__ x, const float* __restrict__ dinv,
                        float* __restrict__ xs, int n, int e) {
    int i = blockIdx.x * blockDim.x + threadIdx.x;
    if (i >= n) { if (i == n) rowptr[n] = e; return; }
    rowptr[i] += bsums[i / SCAN_BLK];
    if (i == 0) rowptr[n] = e;
    float d = __ldg(&dinv[i]);
    const float4* x4 = reinterpret_cast<const float4*>(x) + (size_t)i * 2;
    float4* s4 = reinterpret_cast<float4*>(xs) + (size_t)i * 2;
    float4 a = __ldg(x4), b = __ldg(x4 + 1);
    a.x *= d; a.y *= d; a.z *= d; a.w *= d;
    b.x *= d; b.y *= d; b.z *= d; b.w *= d;
    s4[0] = a; s4[1] = b;
}

__global__ void k_fillcsr(const int* __restrict__ src, const int* __restrict__ dst,
                          const int* __restrict__ rowptr, int* __restrict__ fill,
                          int* __restrict__ col, int e) {
    int i = blockIdx.x * blockDim.x + threadIdx.x;
    if (i >= e) return;
    int d = dst[i];
    int pos = __ldg(&rowptr[d]) + atomicAdd(&fill[d], 1);
    col[pos] = src[i];
}

// counting-sort scatter: block-aggregated per-bin reservation + smem rank
__global__ void k_permfill(const int* __restrict__ deg, const int* __restrict__ hbase,
                           int* __restrict__ hfill, int* __restrict__ perm, int n) {
    __shared__ int sbins[256];
    __shared__ int sbase[256];
    __shared__ int scnt[256];
    int i = blockIdx.x * 256 + threadIdx.x;
    int b = -1;
    if (i < n) { int d = __ldg(&deg[i]); b = d < 255 ? d : 255; }
    sbins[threadIdx.x] = b;
    scnt[threadIdx.x] = 0;
    __syncthreads();
    if (b >= 0) atomicAdd(&scnt[b], 1);
    __syncthreads();
    if (scnt[threadIdx.x] > 0)
        sbase[threadIdx.x] = atomicAdd(&hfill[threadIdx.x], scnt[threadIdx.x]);
    __syncthreads();
    if (b >= 0) {
        int rank = 0;
        for (int j = 0; j < threadIdx.x; j++) rank += (sbins[j] == b);
        perm[__ldg(&hbase[b]) + sbase[b] + rank] = i;
    }
}

// ---------------- head precompose ----------------
__global__ void k_head(const float* __restrict__ W4, const float* __restrict__ b4,
                       const float* __restrict__ Wlin, const float* __restrict__ blin,
                       float* __restrict__ Wc, float* __restrict__ bc) {
    int t = threadIdx.x;
    int i = t >> 2, c = t & 3;
    float s = 0.f;
#pragma unroll 8
    for (int k = 0; k < 128; k++)
        s += __ldg(&W4[i * 128 + k]) * __ldg(&Wlin[k * 4 + c]);
    Wc[i * 4 + c] = s;
    if (i == 0) {
        float b = __ldg(&blin[c]);
#pragma unroll 8
        for (int k = 0; k < 128; k++)
            b += __ldg(&b4[k]) * __ldg(&Wlin[k * 4 + c]);
        bc[c] = b;
    }
}

// ---------------- warp-fused agg + shuffle GEMM + PReLU + prescale ----------
template<int FIN, int FOUT, bool PROJ>
__global__ void __launch_bounds__(256)
k_wlayer(const int* __restrict__ rowptr, const int* __restrict__ col,
         const int* __restrict__ perm,
         const float* __restrict__ hs, const float* __restrict__ dinv,
         const float* __restrict__ W, const float* __restrict__ bias,
         const float* __restrict__ aP, float* __restrict__ out,
         const float* __restrict__ Wc, float* __restrict__ hp, int n) {
    constexpr int TPE = FIN / 4;
    constexpr int NPB = 256 / TPE;
    constexpr int CPL = FOUT / TPE;
    static_assert(CPL == 8, "expect 8 cols/lane");

    __shared__ float Ws[FIN * FOUT];
    __shared__ float bs[FOUT];
    __shared__ float Wcs[PROJ ? FOUT * 4 : 1];
    for (int i = threadIdx.x; i < FIN * FOUT; i += 256) Ws[i] = __ldg(&W[i]);
    if (threadIdx.x < FOUT) bs[threadIdx.x] = __ldg(&bias[threadIdx.x]);
    if (PROJ) {
        for (int i = threadIdx.x; i < FOUT * 4; i += 256) Wcs[i] = __ldg(&Wc[i]);
    }
    float a = __ldg(aP);
    __syncthreads();

    int group = threadIdx.x / TPE;
    int lane  = threadIdx.x % TPE;
    int idx   = blockIdx.x * NPB + group;
    bool live = (idx < n);
    int idx_c = live ? idx : (n - 1);
    int node  = __ldg(&perm[idx_c]);           // degree-sorted node id

    int beg = __ldg(&rowptr[node]);
    int end = __ldg(&rowptr[node + 1]);
    const float4* h4 = reinterpret_cast<const float4*>(hs);
    float4 acc = __ldg(h4 + (size_t)node * TPE + lane);   // self (pre-scaled)
    int p = beg;
    for (; p + 4 <= end; p += 4) {
        int s0 = __ldg(&col[p + 0]);
        int s1 = __ldg(&col[p + 1]);
        int s2 = __ldg(&col[p + 2]);
        int s3 = __ldg(&col[p + 3]);
        float4 v0 = __ldg(h4 + (size_t)s0 * TPE + lane);
        float4 v1 = __ldg(h4 + (size_t)s1 * TPE + lane);
        float4 v2 = __ldg(h4 + (size_t)s2 * TPE + lane);
        float4 v3 = __ldg(h4 + (size_t)s3 * TPE + lane);
        acc.x += v0.x + v1.x + v2.x + v3.x;
        acc.y += v0.y + v1.y + v2.y + v3.y;
        acc.z += v0.z + v1.z + v2.z + v3.z;
        acc.w += v0.w + v1.w + v2.w + v3.w;
    }
    for (; p < end; p++) {
        int s = __ldg(&col[p]);
        float4 v = __ldg(h4 + (size_t)s * TPE + lane);
        acc.x += v.x; acc.y += v.y; acc.z += v.z; acc.w += v.w;
    }
    float dn = __ldg(&dinv[node]);
    float za[4] = {acc.x * dn, acc.y * dn, acc.z * dn, acc.w * dn};

    int lane32 = threadIdx.x & 31;
    int base   = lane32 & ~(TPE - 1);
    int c0 = lane * CPL;
    float4 o0 = *reinterpret_cast<const float4*>(&bs[c0]);
    float4 o1 = *reinterpret_cast<const float4*>(&bs[c0 + 4]);
#pragma unroll
    for (int k4 = 0; k4 < TPE; k4++) {
#pragma unroll
        for (int j = 0; j < 4; j++) {
            float zk = __shfl_sync(0xffffffffu, za[j], base + k4);
            int k = k4 * 4 + j;
            float4 wa = *reinterpret_cast<const float4*>(&Ws[k * FOUT + c0]);
            float4 wb = *reinterpret_cast<const float4*>(&Ws[k * FOUT + c0 + 4]);
            o0.x += zk * wa.x; o0.y += zk * wa.y; o0.z += zk * wa.z; o0.w += zk * wa.w;
            o1.x += zk * wb.x; o1.y += zk * wb.y; o1.z += zk * wb.z; o1.w += zk * wb.w;
        }
    }
    o0.x = o0.x >= 0.f ? o0.x : a * o0.x;
    o0.y = o0.y >= 0.f ? o0.y : a * o0.y;
    o0.z = o0.z >= 0.f ? o0.z : a * o0.z;
    o0.w = o0.w >= 0.f ? o0.w : a * o0.w;
    o1.x = o1.x >= 0.f ? o1.x : a * o1.x;
    o1.y = o1.y >= 0.f ? o1.y : a * o1.y;
    o1.z = o1.z >= 0.f ? o1.z : a * o1.z;
    o1.w = o1.w >= 0.f ? o1.w : a * o1.w;
    o0.x *= dn; o0.y *= dn; o0.z *= dn; o0.w *= dn;
    o1.x *= dn; o1.y *= dn; o1.z *= dn; o1.w *= dn;
    if (live) {
        float4* orow = reinterpret_cast<float4*>(out + (size_t)node * FOUT + c0);
        orow[0] = o0;
        orow[1] = o1;
    }

    if (PROJ) {
        float pj[4] = {0.f, 0.f, 0.f, 0.f};
        float hvals[8] = {o0.x, o0.y, o0.z, o0.w, o1.x, o1.y, o1.z, o1.w};
#pragma unroll
        for (int j = 0; j < 8; j++) {
            float4 w = *reinterpret_cast<const float4*>(&Wcs[(c0 + j) * 4]);
            pj[0] += hvals[j] * w.x; pj[1] += hvals[j] * w.y;
            pj[2] += hvals[j] * w.z; pj[3] += hvals[j] * w.w;
        }
#pragma unroll
        for (int off = TPE / 2; off > 0; off >>= 1) {
#pragma unroll
            for (int j = 0; j < 4; j++)
                pj[j] += __shfl_xor_sync(0xffffffffu, pj[j], off);
        }
        if (live && lane == 0) {
            float4 r = {pj[0], pj[1], pj[2], pj[3]};
            reinterpret_cast<float4*>(hp)[node] = r;
        }
    }
}

// ---------------- fused layer-4 agg (4-wide) + graph pooling ----------------
__global__ void __launch_bounds__(256)
k_z4pool(const int* __restrict__ rowptr, const int* __restrict__ col,
         const int* __restrict__ perm,
         const float* __restrict__ hp, const float* __restrict__ dinv,
         const int* __restrict__ batch, float* __restrict__ accum, int n) {
    __shared__ float acc_s[64 * 4];
    if (threadIdx.x < 256) acc_s[threadIdx.x] = 0.f;
    __syncthreads();

    int i = blockIdx.x * blockDim.x + threadIdx.x;
    if (i < n) {
        int node = __ldg(&perm[i]);
        const float4* hp4 = reinterpret_cast<const float4*>(hp);
        float4 acc = __ldg(hp4 + node);
        int beg = __ldg(&rowptr[node]);
        int end = __ldg(&rowptr[node + 1]);
        int p = beg;
        for (; p + 4 <= end; p += 4) {
            int s0 = __ldg(&col[p + 0]);
            int s1 = __ldg(&col[p + 1]);
            int s2 = __ldg(&col[p + 2]);
            int s3 = __ldg(&col[p + 3]);
            float4 v0 = __ldg(hp4 + s0);
            float4 v1 = __ldg(hp4 + s1);
            float4 v2 = __ldg(hp4 + s2);
            float4 v3 = __ldg(hp4 + s3);
            acc.x += v0.x + v1.x + v2.x + v3.x;
            acc.y += v0.y + v1.y + v2.y + v3.y;
            acc.z += v0.z + v1.z + v2.z + v3.z;
            acc.w += v0.w + v1.w + v2.w + v3.w;
        }
        for (; p < end; p++) {
            int s = __ldg(&col[p]);
            float4 v = __ldg(hp4 + s);
            acc.x += v.x; acc.y += v.y; acc.z += v.z; acc.w += v.w;
        }
        float d = __ldg(&dinv[node]);
        int g = __ldg(&batch[node]);
        atomicAdd(&acc_s[g * 4 + 0], acc.x * d);
        atomicAdd(&acc_s[g * 4 + 1], acc.y * d);
        atomicAdd(&acc_s[g * 4 + 2], acc.z * d);
        atomicAdd(&acc_s[g * 4 + 3], acc.w * d);
    }
    __syncthreads();
    if (threadIdx.x < 256) {
        float v = acc_s[threadIdx.x];
        if (v != 0.f) atomicAdd(&accum[threadIdx.x], v);
    }
}

// ---------------- finish ----------------
__device__ __forceinline__ int lower_bound_i(const int* b, int n, int v) {
    int lo = 0, hi = n;
    while (lo < hi) {
        int m = (lo + hi) >> 1;
        if (__ldg(&b[m]) < v) lo = m + 1; else hi = m;
    }
    return lo;
}

__global__ void k_finish(const float* __restrict__ accum, const int* __restrict__ batch,
                         const float* __restrict__ bc, float* __restrict__ out,
                         int n, int G) {
    int t = threadIdx.x;
    int g = t >> 2, c = t & 3;
    if (g >= G) return;
    int start = lower_bound_i(batch, n, g);
    int end   = lower_bound_i(batch, n, g + 1);
    int cnt = end - start;
    float denom = (float)(cnt > 1 ? cnt : 1);
    out[g * 4 + c] = accum[g * 4 + c] / denom + __ldg(&bc[c]);
}

// ---------------------------------------------------------------------------
extern "C" void kernel_launch(void* const* d_in, const int* in_sizes, int n_in,
                              void* d_out, int out_size) {
    const float* x    = (const float*)d_in[0];
    const int* esrc   = (const int*)d_in[1];
    const int* edst   = (const int*)d_in[2];
    const int* batch  = (const int*)d_in[3];
    const float* W1   = (const float*)d_in[4];
    const float* b1   = (const float*)d_in[5];
    const float* W2   = (const float*)d_in[6];
    const float* b2   = (const float*)d_in[7];
    const float* W3   = (const float*)d_in[8];
    const float* b3   = (const float*)d_in[9];
    const float* W4   = (const float*)d_in[10];
    const float* b4   = (const float*)d_in[11];
    const float* a1   = (const float*)d_in[12];
    const float* a2   = (const float*)d_in[13];
    const float* a3   = (const float*)d_in[14];
    const float* Wlin = (const float*)d_in[15];
    const float* blin = (const float*)d_in[16];
    float* out = (float*)d_out;

    int n = in_sizes[0] / 8;
    int e = in_sizes[1];
    int G = out_size / 4;

    float *dinv, *xs, *ha, *hb, *hp, *accum, *Wc, *bc;
    int *deg, *fill, *rowptr, *bsums, *col, *hist, *hbase, *hfill, *perm;
    cudaGetSymbolAddress((void**)&dinv,   g_dinv);
    cudaGetSymbolAddress((void**)&deg,    g_deg);
    cudaGetSymbolAddress((void**)&fill,   g_fill);
    cudaGetSymbolAddress((void**)&rowptr, g_rowptr);
    cudaGetSymbolAddress((void**)&bsums,  g_bsums);
    cudaGetSymbolAddress((void**)&hist,   g_hist);
    cudaGetSymbolAddress((void**)&hbase,  g_hbase);
    cudaGetSymbolAddress((void**)&hfill,  g_hfill);
    cudaGetSymbolAddress((void**)&perm,   g_perm);
    cudaGetSymbolAddress((void**)&col,    g_col);
    cudaGetSymbolAddress((void**)&xs,     g_xs);
    cudaGetSymbolAddress((void**)&ha,     g_ha);
    cudaGetSymbolAddress((void**)&hb,     g_hb);
    cudaGetSymbolAddress((void**)&hp,     g_hp);
    cudaGetSymbolAddress((void**)&accum,  g_accum);
    cudaGetSymbolAddress((void**)&Wc,     g_Wc);
    cudaGetSymbolAddress((void**)&bc,     g_bc);

    const int T = 256;
    int nscan = cdiv(n, SCAN_BLK);

    k_zero   <<<cdiv(n, T), T>>>(deg, fill, hist, hfill, accum, n);
    k_count  <<<cdiv(e, T), T>>>(edst, deg, e);
    k_scan1  <<<nscan, SCAN_BLK>>>(deg, rowptr, bsums, dinv, hist, n);
    k_scan2  <<<1, 256>>>(bsums, hist, hbase, nscan);
    k_scan3  <<<cdiv(n + 1, T), T>>>(rowptr, bsums, x, dinv, xs, n, e);
    k_fillcsr<<<cdiv(e, T), T>>>(esrc, edst, rowptr, fill, col, e);
    k_permfill<<<cdiv(n, T), T>>>(deg, hbase, hfill, perm, n);
    k_head   <<<1, 256>>>(W4, b4, Wlin, blin, Wc, bc);

    // Layers 1-3: warp-fused agg + shuffle GEMM on degree-sorted nodes
    k_wlayer<8, 16, false><<<cdiv(n, 128), T>>>(rowptr, col, perm, xs, dinv, W1, b1, a1, ha, nullptr, nullptr, n);
    k_wlayer<16, 32, false><<<cdiv(n, 64), T>>>(rowptr, col, perm, ha, dinv, W2, b2, a2, hb, nullptr, nullptr, n);
    k_wlayer<32, 64, true> <<<cdiv(n, 32), T>>>(rowptr, col, perm, hb, dinv, W3, b3, a3, ha, Wc, hp, n);

    // Layer 4 (4-wide) + pooling fused; then finish
    k_z4pool<<<cdiv(n, T), T>>>(rowptr, col, perm, hp, dinv, batch, accum, n);
    k_finish<<<1, 256>>>(accum, batch, bc, out, n, G);
}